// round 7
// baseline (speedup 1.0000x reference)
#include <cuda_runtime.h>
#include <cuda_bf16.h>
#include <stdint.h>
#include <math.h>

#define KEXP 8
#define NROWS_MAX 1000000
#define NSLICE 37
#define GRID (KEXP * NSLICE)
#define TPB 256
#define ROWS_PER_BLOCK 128   // 8 warps * 16 rows

// ---------------- device scratch ---------------------------------------------
__device__ int g_counts[KEXP];
__device__ int g_off[KEXP + 1];
__device__ int g_cursor[KEXP];
__device__ int g_ticket;
__device__ int g_perm[NROWS_MAX];

// ---------------- helpers -----------------------------------------------------
__device__ __forceinline__ uint32_t pk2(float lo, float hi) {
    uint32_t d;
    asm("cvt.rn.bf16x2.f32 %0, %1, %2;" : "=r"(d) : "f"(hi), "f"(lo));
    return d;
}
__device__ __forceinline__ void split_pair(float v0, float v1,
                                           uint32_t& ph, uint32_t& pl) {
    ph = pk2(v0, v1);
    float r0 = v0 - __uint_as_float(ph << 16);
    float r1 = v1 - __uint_as_float(ph & 0xffff0000u);
    pl = pk2(r0, r1);
}

__device__ __forceinline__ void mma_bf16(float* C, const uint32_t* a,
                                         uint32_t b0, uint32_t b1) {
    asm volatile(
        "mma.sync.aligned.m16n8k16.row.col.f32.bf16.bf16.f32 "
        "{%0,%1,%2,%3}, {%4,%5,%6,%7}, {%8,%9}, {%0,%1,%2,%3};"
        : "+f"(C[0]), "+f"(C[1]), "+f"(C[2]), "+f"(C[3])
        : "r"(a[0]), "r"(a[1]), "r"(a[2]), "r"(a[3]), "r"(b0), "r"(b1));
}

__device__ __forceinline__ float softplus_f(float v) {
    return fmaxf(v, 0.f) + __logf(1.f + __expf(-fabsf(v)));
}

// ---------------- bucketing (proven R5 kernels, no grid-wide spin) ------------
__global__ void k_hist(const int* __restrict__ y, int n) {
    __shared__ int s[8][KEXP];
    int tid = threadIdx.x, wid = tid >> 5;
    if (tid < 8 * KEXP) ((int*)s)[tid] = 0;
    __syncthreads();
    int total = gridDim.x * blockDim.x;
    for (int i = blockIdx.x * blockDim.x + tid; i < n; i += total)
        atomicAdd(&s[wid][y[i]], 1);
    __syncthreads();
    if (tid < KEXP) {
        int acc = 0;
#pragma unroll
        for (int w = 0; w < 8; w++) acc += s[w][tid];
        atomicAdd(&g_counts[tid], acc);
    }
    __threadfence();
    if (tid == 0) {
        if (atomicAdd(&g_ticket, 1) == (int)gridDim.x - 1) {
            int o = 0;
#pragma unroll
            for (int k = 0; k < KEXP; k++) {
                g_off[k] = o;
                g_cursor[k] = o;
                o += g_counts[k];
                g_counts[k] = 0;   // reset for next graph replay
            }
            g_off[KEXP] = o;
            g_ticket = 0;
        }
    }
}

#define SC_ELEMS 2048
__global__ void k_scatter(const int* __restrict__ y, int n) {
    __shared__ int cache[SC_ELEMS];
    __shared__ int shist[KEXP];
    __shared__ int scur[KEXP];
    int base = blockIdx.x * SC_ELEMS;
    int cnt = n - base;
    if (cnt > SC_ELEMS) cnt = SC_ELEMS;
    if (cnt <= 0) return;
    int tid = threadIdx.x;
    if (tid < KEXP) shist[tid] = 0;
    __syncthreads();
    for (int i = tid; i < cnt; i += blockDim.x) {
        int k = y[base + i];
        cache[i] = k;
        atomicAdd(&shist[k], 1);
    }
    __syncthreads();
    if (tid < KEXP) scur[tid] = atomicAdd(&g_cursor[tid], shist[tid]);
    __syncthreads();
    for (int i = tid; i < cnt; i += blockDim.x) {
        int slot = atomicAdd(&scur[cache[i]], 1);
        g_perm[slot] = base + i;
    }
}

// ---------------- main mma.sync MLP kernel ------------------------------------
// Weight fragments packed as uint4 (b0h, b1h, b0l, b1l), idx = ((kk*NJ+j)*4+c)*8+g
// -> one LDS.128 per (kk,j) per thread, conflict-free.

__global__ void __launch_bounds__(TPB, 2)
k_main(const float* __restrict__ x,
       const float* __restrict__ W1, const float* __restrict__ b1,
       const float* __restrict__ W2, const float* __restrict__ b2,
       const float* __restrict__ W3, const float* __restrict__ b3,
       float* __restrict__ out, int n)
{
    __shared__ uint4 wq1[2 * 8 * 32];   // K=32 (2 kfrags), N=64
    __shared__ uint4 wq2[4 * 8 * 32];   // K=64, N=64
    __shared__ uint4 wq3[4 * 4 * 32];   // K=64, N=32
    __shared__ float biasS[192];        // b1[0:64] b2[64:128] b3[128:160]

    int tid = threadIdx.x;
    int e = blockIdx.x & 7;
    int slice = blockIdx.x >> 3;

    const float* W1k = W1 + e * 2048;   // [32][64]
    const float* W2k = W2 + e * 4096;   // [64][64]
    const float* W3k = W3 + e * 2048;   // [64][32]

    // ---- stage packed weight fragments ----
    for (int i = tid; i < 512; i += TPB) {          // L1: kk<2, j<8
        int g = i & 7, c = (i >> 3) & 3, j = (i >> 5) & 7, kk = i >> 8;
        int nn = 8 * j + g, kb = 16 * kk + 2 * c;
        uint4 q;
        split_pair(W1k[kb * 64 + nn], W1k[(kb + 1) * 64 + nn], q.x, q.z);
        split_pair(W1k[(kb + 8) * 64 + nn], W1k[(kb + 9) * 64 + nn], q.y, q.w);
        wq1[i] = q;
    }
    for (int i = tid; i < 1024; i += TPB) {         // L2: kk<4, j<8
        int g = i & 7, c = (i >> 3) & 3, j = (i >> 5) & 7, kk = i >> 8;
        int nn = 8 * j + g, kb = 16 * kk + 2 * c;
        uint4 q;
        split_pair(W2k[kb * 64 + nn], W2k[(kb + 1) * 64 + nn], q.x, q.z);
        split_pair(W2k[(kb + 8) * 64 + nn], W2k[(kb + 9) * 64 + nn], q.y, q.w);
        wq2[i] = q;
    }
    for (int i = tid; i < 512; i += TPB) {          // L3: kk<4, j<4
        int g = i & 7, c = (i >> 3) & 3, j = (i >> 5) & 3, kk = i >> 7;
        int nn = 8 * j + g, kb = 16 * kk + 2 * c;
        uint4 q;
        split_pair(W3k[kb * 32 + nn], W3k[(kb + 1) * 32 + nn], q.x, q.z);
        split_pair(W3k[(kb + 8) * 32 + nn], W3k[(kb + 9) * 32 + nn], q.y, q.w);
        wq3[i] = q;
    }
    if (tid < 64) biasS[tid] = b1[e * 64 + tid];
    else if (tid < 128) biasS[tid] = b2[e * 64 + (tid - 64)];
    else if (tid < 160) biasS[128 + tid - 128] = b3[e * 32 + (tid - 128)];
    __syncthreads();

    int w = tid >> 5;
    int lane = tid & 31;
    int g = lane >> 2;
    int c = lane & 3;
    int cg = c * 8 + g;        // per-thread fragment slot

    const uint4* q1 = wq1 + cg;
    const uint4* q2 = wq2 + cg;
    const uint4* q3 = wq3 + cg;

    int off0 = g_off[e];
    int cnt = g_off[e + 1] - off0;
    int ntile = (cnt + ROWS_PER_BLOCK - 1) >> 7;

    for (int t = slice; t < ntile; t += NSLICE) {
        int wbase = t * ROWS_PER_BLOCK + w * 16;
        if (wbase >= cnt) continue;

        int rows[2];
        bool valid[2];
#pragma unroll
        for (int hh = 0; hh < 2; hh++) {
            int gi = wbase + hh * 8 + g;
            valid[hh] = gi < cnt;
            rows[hh] = g_perm[off0 + (gi < cnt ? gi : cnt - 1)];
        }

        // ---- layer 1 A fragments from x ----
        uint32_t a1h[2][4], a1l[2][4];
#pragma unroll
        for (int hh = 0; hh < 2; hh++) {
            const float* xr = x + (size_t)rows[hh] * 32;
#pragma unroll
            for (int kk = 0; kk < 2; kk++) {
                float2 p0 = *(const float2*)(xr + 2 * c + 16 * kk);
                float2 p1 = *(const float2*)(xr + 2 * c + 8 + 16 * kk);
                split_pair(p0.x, p0.y, a1h[kk][hh],     a1l[kk][hh]);
                split_pair(p1.x, p1.y, a1h[kk][2 + hh], a1l[kk][2 + hh]);
            }
        }

        // ---- layer 1: [16x32] @ [32x64] ----
        float C1[8][4];
#pragma unroll
        for (int j = 0; j < 8; j++) {
            float2 bb = *(const float2*)(biasS + 8 * j + 2 * c);
            C1[j][0] = bb.x; C1[j][1] = bb.y; C1[j][2] = bb.x; C1[j][3] = bb.y;
        }
#pragma unroll
        for (int kk = 0; kk < 2; kk++) {
#pragma unroll
            for (int j = 0; j < 8; j++) {
                uint4 q = q1[(kk * 8 + j) * 32];
                mma_bf16(C1[j], a1h[kk], q.x, q.y);
                mma_bf16(C1[j], a1l[kk], q.x, q.y);
                mma_bf16(C1[j], a1h[kk], q.z, q.w);
            }
        }

        // ---- relu + convert -> layer 2 A ----
        uint32_t a2h[4][4], a2l[4][4];
#pragma unroll
        for (int j = 0; j < 8; j++) {
            float v0 = fmaxf(C1[j][0], 0.f);
            float v1 = fmaxf(C1[j][1], 0.f);
            float v2 = fmaxf(C1[j][2], 0.f);
            float v3 = fmaxf(C1[j][3], 0.f);
            int kk = j >> 1, half = j & 1;
            split_pair(v0, v1, a2h[kk][2 * half],     a2l[kk][2 * half]);
            split_pair(v2, v3, a2h[kk][2 * half + 1], a2l[kk][2 * half + 1]);
        }

        // ---- layer 2: [16x64] @ [64x64] ----
        float C2[8][4];
#pragma unroll
        for (int j = 0; j < 8; j++) {
            float2 bb = *(const float2*)(biasS + 64 + 8 * j + 2 * c);
            C2[j][0] = bb.x; C2[j][1] = bb.y; C2[j][2] = bb.x; C2[j][3] = bb.y;
        }
#pragma unroll
        for (int kk = 0; kk < 4; kk++) {
#pragma unroll
            for (int j = 0; j < 8; j++) {
                uint4 q = q2[(kk * 8 + j) * 32];
                mma_bf16(C2[j], a2h[kk], q.x, q.y);
                mma_bf16(C2[j], a2l[kk], q.x, q.y);
                mma_bf16(C2[j], a2h[kk], q.z, q.w);
            }
        }

        // ---- relu + convert -> layer 3 A ----
        uint32_t a3h[4][4], a3l[4][4];
#pragma unroll
        for (int j = 0; j < 8; j++) {
            float v0 = fmaxf(C2[j][0], 0.f);
            float v1 = fmaxf(C2[j][1], 0.f);
            float v2 = fmaxf(C2[j][2], 0.f);
            float v3 = fmaxf(C2[j][3], 0.f);
            int kk = j >> 1, half = j & 1;
            split_pair(v0, v1, a3h[kk][2 * half],     a3l[kk][2 * half]);
            split_pair(v2, v3, a3h[kk][2 * half + 1], a3l[kk][2 * half + 1]);
        }

        // ---- layer 3: [16x64] @ [64x32] ----
        float C3[4][4];
#pragma unroll
        for (int j = 0; j < 4; j++) {
            float2 bb = *(const float2*)(biasS + 128 + 8 * j + 2 * c);
            C3[j][0] = bb.x; C3[j][1] = bb.y; C3[j][2] = bb.x; C3[j][3] = bb.y;
        }
#pragma unroll
        for (int kk = 0; kk < 4; kk++) {
#pragma unroll
            for (int j = 0; j < 4; j++) {
                uint4 q = q3[(kk * 4 + j) * 32];
                mma_bf16(C3[j], a3h[kk], q.x, q.y);
                mma_bf16(C3[j], a3l[kk], q.x, q.y);
                mma_bf16(C3[j], a3h[kk], q.z, q.w);
            }
        }

        // ---- epilogue: mu (tiles 0,1), sigma = softplus (tiles 2,3) ----
#pragma unroll
        for (int j = 0; j < 4; j++) {
            float v0 = C3[j][0], v1 = C3[j][1], v2 = C3[j][2], v3 = C3[j][3];
            size_t colbase;
            if (j < 2) {
                colbase = 8 * j + 2 * c;
            } else {
                v0 = softplus_f(v0); v1 = softplus_f(v1);
                v2 = softplus_f(v2); v3 = softplus_f(v3);
                colbase = (size_t)n * 16 + 8 * (j - 2) + 2 * c;
            }
            if (valid[0])
                *(float2*)(out + (size_t)rows[0] * 16 + colbase) = make_float2(v0, v1);
            if (valid[1])
                *(float2*)(out + (size_t)rows[1] * 16 + colbase) = make_float2(v2, v3);
        }
    }
}

// ---------------- launch ------------------------------------------------------
extern "C" void kernel_launch(void* const* d_in, const int* in_sizes, int n_in,
                              void* d_out, int out_size) {
    const float* x  = (const float*)d_in[0];
    const int*   y  = (const int*)d_in[1];
    const float* W1 = (const float*)d_in[2];
    const float* b1 = (const float*)d_in[3];
    const float* W2 = (const float*)d_in[4];
    const float* b2 = (const float*)d_in[5];
    const float* W3 = (const float*)d_in[6];
    const float* b3 = (const float*)d_in[7];
    float* out = (float*)d_out;
    int n = in_sizes[1];

    k_hist<<<512, 256>>>(y, n);
    k_scatter<<<(n + SC_ELEMS - 1) / SC_ELEMS, 256>>>(y, n);
    k_main<<<GRID, TPB>>>(x, W1, b1, W2, b2, W3, b3, out, n);
}

// round 8
// speedup vs baseline: 1.6838x; 1.6838x over previous
#include <cuda_runtime.h>
#include <cuda_bf16.h>
#include <stdint.h>
#include <math.h>

#define KEXP 8
#define NROWS_MAX 1000000
#define NSLICE 37
#define GRID (KEXP * NSLICE)
#define TPB 256
#define ROWS_PER_BLOCK 128   // 8 warps * 16 rows

// ---------------- device scratch ---------------------------------------------
__device__ int g_counts[KEXP];
__device__ int g_off[KEXP + 1];
__device__ int g_cursor[KEXP];
__device__ int g_ticket;
__device__ int g_perm[NROWS_MAX];

// ---------------- helpers -----------------------------------------------------
__device__ __forceinline__ uint32_t pk2(float lo, float hi) {
    uint32_t d;
    asm("cvt.rn.bf16x2.f32 %0, %1, %2;" : "=r"(d) : "f"(hi), "f"(lo));
    return d;
}
__device__ __forceinline__ void split_pair(float v0, float v1,
                                           uint32_t& ph, uint32_t& pl) {
    ph = pk2(v0, v1);
    float r0 = v0 - __uint_as_float(ph << 16);
    float r1 = v1 - __uint_as_float(ph & 0xffff0000u);
    pl = pk2(r0, r1);
}

__device__ __forceinline__ void mma_bf16(float* C, const uint32_t* a,
                                         uint32_t b0, uint32_t b1) {
    asm volatile(
        "mma.sync.aligned.m16n8k16.row.col.f32.bf16.bf16.f32 "
        "{%0,%1,%2,%3}, {%4,%5,%6,%7}, {%8,%9}, {%0,%1,%2,%3};"
        : "+f"(C[0]), "+f"(C[1]), "+f"(C[2]), "+f"(C[3])
        : "r"(a[0]), "r"(a[1]), "r"(a[2]), "r"(a[3]), "r"(b0), "r"(b1));
}

__device__ __forceinline__ float softplus_f(float v) {
    return fmaxf(v, 0.f) + __logf(1.f + __expf(-fabsf(v)));
}

// ---------------- bucketing (proven R5 kernels) -------------------------------
__global__ void k_hist(const int* __restrict__ y, int n) {
    __shared__ int s[8][KEXP];
    int tid = threadIdx.x, wid = tid >> 5;
    if (tid < 8 * KEXP) ((int*)s)[tid] = 0;
    __syncthreads();
    int total = gridDim.x * blockDim.x;
    for (int i = blockIdx.x * blockDim.x + tid; i < n; i += total)
        atomicAdd(&s[wid][y[i]], 1);
    __syncthreads();
    if (tid < KEXP) {
        int acc = 0;
#pragma unroll
        for (int w = 0; w < 8; w++) acc += s[w][tid];
        atomicAdd(&g_counts[tid], acc);
    }
    __threadfence();
    if (tid == 0) {
        if (atomicAdd(&g_ticket, 1) == (int)gridDim.x - 1) {
            int o = 0;
#pragma unroll
            for (int k = 0; k < KEXP; k++) {
                g_off[k] = o;
                g_cursor[k] = o;
                o += g_counts[k];
                g_counts[k] = 0;   // reset for next graph replay
            }
            g_off[KEXP] = o;
            g_ticket = 0;
        }
    }
}

#define SC_ELEMS 2048
__global__ void k_scatter(const int* __restrict__ y, int n) {
    __shared__ int cache[SC_ELEMS];
    __shared__ int shist[KEXP];
    __shared__ int scur[KEXP];
    int base = blockIdx.x * SC_ELEMS;
    int cnt = n - base;
    if (cnt > SC_ELEMS) cnt = SC_ELEMS;
    if (cnt <= 0) return;
    int tid = threadIdx.x;
    if (tid < KEXP) shist[tid] = 0;
    __syncthreads();
    for (int i = tid; i < cnt; i += blockDim.x) {
        int k = y[base + i];
        cache[i] = k;
        atomicAdd(&shist[k], 1);
    }
    __syncthreads();
    if (tid < KEXP) scur[tid] = atomicAdd(&g_cursor[tid], shist[tid]);
    __syncthreads();
    for (int i = tid; i < cnt; i += blockDim.x) {
        int slot = atomicAdd(&scur[cache[i]], 1);
        g_perm[slot] = base + i;
    }
}

// ---------------- main mma.sync MLP kernel ------------------------------------
#define PADN 72   // stride 72 words: bank = (8c+g) -> conflict-free

__global__ void __launch_bounds__(TPB, 2)
k_main(const float* __restrict__ x,
       const float* __restrict__ W1, const float* __restrict__ b1,
       const float* __restrict__ W2, const float* __restrict__ b2,
       const float* __restrict__ W3, const float* __restrict__ b3,
       float* __restrict__ out, int n)
{
    __shared__ uint32_t wp1h[16 * PADN], wp1l[16 * PADN];
    __shared__ uint32_t wp2h[32 * PADN], wp2l[32 * PADN];
    __shared__ uint32_t wp3h[32 * PADN], wp3l[32 * PADN];
    __shared__ float biasS[192];   // b1[0:64] b2[64:128] b3[128:160]

    int tid = threadIdx.x;
    int e = blockIdx.x & 7;
    int slice = blockIdx.x >> 3;

    const float* W1k = W1 + e * 2048;   // [32][64]
    const float* W2k = W2 + e * 4096;   // [64][64]
    const float* W3k = W3 + e * 2048;   // [64][32]

    // ---- stage weights as bf16 hi/lo, k-pair packed for B fragments ----
    for (int i = tid; i < 2048; i += TPB) {           // W1: K=32, N=64
        int k = i >> 6, nn = i & 63;
        float v = W1k[i];
        unsigned short h = __bfloat16_as_ushort(__float2bfloat16_rn(v));
        float hv = __uint_as_float(((uint32_t)h) << 16);
        unsigned short l = __bfloat16_as_ushort(__float2bfloat16_rn(v - hv));
        int idx = ((k >> 1) * PADN + nn) * 2 + (k & 1);
        ((unsigned short*)wp1h)[idx] = h;
        ((unsigned short*)wp1l)[idx] = l;
    }
    for (int i = tid; i < 4096; i += TPB) {           // W2: K=64, N=64
        int k = i >> 6, nn = i & 63;
        float v = W2k[i];
        unsigned short h = __bfloat16_as_ushort(__float2bfloat16_rn(v));
        float hv = __uint_as_float(((uint32_t)h) << 16);
        unsigned short l = __bfloat16_as_ushort(__float2bfloat16_rn(v - hv));
        int idx = ((k >> 1) * PADN + nn) * 2 + (k & 1);
        ((unsigned short*)wp2h)[idx] = h;
        ((unsigned short*)wp2l)[idx] = l;
    }
    for (int i = tid; i < 2048; i += TPB) {           // W3: K=64, N=32
        int k = i >> 5, nn = i & 31;
        float v = W3k[i];
        unsigned short h = __bfloat16_as_ushort(__float2bfloat16_rn(v));
        float hv = __uint_as_float(((uint32_t)h) << 16);
        unsigned short l = __bfloat16_as_ushort(__float2bfloat16_rn(v - hv));
        int idx = ((k >> 1) * PADN + nn) * 2 + (k & 1);
        ((unsigned short*)wp3h)[idx] = h;
        ((unsigned short*)wp3l)[idx] = l;
    }
    if (tid < 64) biasS[tid] = b1[e * 64 + tid];
    else if (tid < 128) biasS[tid] = b2[e * 64 + (tid - 64)];
    else if (tid < 160) biasS[128 + tid - 128] = b3[e * 32 + (tid - 128)];
    __syncthreads();

    int w = tid >> 5;
    int lane = tid & 31;
    int g = lane >> 2;          // groupID (fragment row)
    int c = lane & 3;           // threadID in group (fragment col pair)

    int off0 = g_off[e];
    int cnt = g_off[e + 1] - off0;
    int ntile = (cnt + ROWS_PER_BLOCK - 1) >> 7;

    for (int t = slice; t < ntile; t += NSLICE) {
        int wbase = t * ROWS_PER_BLOCK + w * 16;
        if (wbase >= cnt) continue;

        int rows[2];
        bool valid[2];
#pragma unroll
        for (int hh = 0; hh < 2; hh++) {
            int gi = wbase + hh * 8 + g;
            valid[hh] = gi < cnt;
            rows[hh] = g_perm[off0 + (gi < cnt ? gi : cnt - 1)];
        }

        // ---- layer 1 A fragments from x (hi/lo split) ----
        uint32_t a1h[2][4], a1l[2][4];
#pragma unroll
        for (int hh = 0; hh < 2; hh++) {
            const float* xr = x + (size_t)rows[hh] * 32;
#pragma unroll
            for (int kk = 0; kk < 2; kk++) {
                float2 p0 = *(const float2*)(xr + 2 * c + 16 * kk);
                float2 p1 = *(const float2*)(xr + 2 * c + 8 + 16 * kk);
                split_pair(p0.x, p0.y, a1h[kk][hh],     a1l[kk][hh]);
                split_pair(p1.x, p1.y, a1h[kk][2 + hh], a1l[kk][2 + hh]);
            }
        }

        // ---- layer 1: [16x32] @ [32x64]  pass-major (no same-C RAW chains) ----
        float C1[8][4];
#pragma unroll
        for (int j = 0; j < 8; j++) {
            float2 bb = *(const float2*)(biasS + 8 * j + 2 * c);
            C1[j][0] = bb.x; C1[j][1] = bb.y; C1[j][2] = bb.x; C1[j][3] = bb.y;
        }
#pragma unroll
        for (int kk = 0; kk < 2; kk++) {
            uint32_t bq0[8], bq1[8];
#pragma unroll
            for (int j = 0; j < 8; j++) {
                int bi = (8 * kk + c) * PADN + 8 * j + g;
                bq0[j] = wp1h[bi]; bq1[j] = wp1h[bi + 4 * PADN];
            }
#pragma unroll
            for (int j = 0; j < 8; j++) mma_bf16(C1[j], a1h[kk], bq0[j], bq1[j]);
#pragma unroll
            for (int j = 0; j < 8; j++) mma_bf16(C1[j], a1l[kk], bq0[j], bq1[j]);
#pragma unroll
            for (int j = 0; j < 8; j++) {
                int bi = (8 * kk + c) * PADN + 8 * j + g;
                bq0[j] = wp1l[bi]; bq1[j] = wp1l[bi + 4 * PADN];
            }
#pragma unroll
            for (int j = 0; j < 8; j++) mma_bf16(C1[j], a1h[kk], bq0[j], bq1[j]);
        }

        // ---- relu + convert -> layer 2 A ----
        uint32_t a2h[4][4], a2l[4][4];
#pragma unroll
        for (int j = 0; j < 8; j++) {
            float v0 = fmaxf(C1[j][0], 0.f);
            float v1 = fmaxf(C1[j][1], 0.f);
            float v2 = fmaxf(C1[j][2], 0.f);
            float v3 = fmaxf(C1[j][3], 0.f);
            int kk = j >> 1, half = j & 1;
            split_pair(v0, v1, a2h[kk][2 * half],     a2l[kk][2 * half]);
            split_pair(v2, v3, a2h[kk][2 * half + 1], a2l[kk][2 * half + 1]);
        }

        // ---- layer 2: [16x64] @ [64x64]  pass-major ----
        float C2[8][4];
#pragma unroll
        for (int j = 0; j < 8; j++) {
            float2 bb = *(const float2*)(biasS + 64 + 8 * j + 2 * c);
            C2[j][0] = bb.x; C2[j][1] = bb.y; C2[j][2] = bb.x; C2[j][3] = bb.y;
        }
#pragma unroll
        for (int kk = 0; kk < 4; kk++) {
            uint32_t bq0[8], bq1[8];
#pragma unroll
            for (int j = 0; j < 8; j++) {
                int bi = (8 * kk + c) * PADN + 8 * j + g;
                bq0[j] = wp2h[bi]; bq1[j] = wp2h[bi + 4 * PADN];
            }
#pragma unroll
            for (int j = 0; j < 8; j++) mma_bf16(C2[j], a2h[kk], bq0[j], bq1[j]);
#pragma unroll
            for (int j = 0; j < 8; j++) mma_bf16(C2[j], a2l[kk], bq0[j], bq1[j]);
#pragma unroll
            for (int j = 0; j < 8; j++) {
                int bi = (8 * kk + c) * PADN + 8 * j + g;
                bq0[j] = wp2l[bi]; bq1[j] = wp2l[bi + 4 * PADN];
            }
#pragma unroll
            for (int j = 0; j < 8; j++) mma_bf16(C2[j], a2h[kk], bq0[j], bq1[j]);
        }

        // ---- relu + convert -> layer 3 A ----
        uint32_t a3h[4][4], a3l[4][4];
#pragma unroll
        for (int j = 0; j < 8; j++) {
            float v0 = fmaxf(C2[j][0], 0.f);
            float v1 = fmaxf(C2[j][1], 0.f);
            float v2 = fmaxf(C2[j][2], 0.f);
            float v3 = fmaxf(C2[j][3], 0.f);
            int kk = j >> 1, half = j & 1;
            split_pair(v0, v1, a3h[kk][2 * half],     a3l[kk][2 * half]);
            split_pair(v2, v3, a3h[kk][2 * half + 1], a3l[kk][2 * half + 1]);
        }

        // ---- layer 3: [16x64] @ [64x32]  pass-major ----
        float C3[4][4];
#pragma unroll
        for (int j = 0; j < 4; j++) {
            float2 bb = *(const float2*)(biasS + 128 + 8 * j + 2 * c);
            C3[j][0] = bb.x; C3[j][1] = bb.y; C3[j][2] = bb.x; C3[j][3] = bb.y;
        }
#pragma unroll
        for (int kk = 0; kk < 4; kk++) {
            uint32_t bq0[4], bq1[4];
#pragma unroll
            for (int j = 0; j < 4; j++) {
                int bi = (8 * kk + c) * PADN + 8 * j + g;
                bq0[j] = wp3h[bi]; bq1[j] = wp3h[bi + 4 * PADN];
            }
#pragma unroll
            for (int j = 0; j < 4; j++) mma_bf16(C3[j], a3h[kk], bq0[j], bq1[j]);
#pragma unroll
            for (int j = 0; j < 4; j++) mma_bf16(C3[j], a3l[kk], bq0[j], bq1[j]);
#pragma unroll
            for (int j = 0; j < 4; j++) {
                int bi = (8 * kk + c) * PADN + 8 * j + g;
                bq0[j] = wp3l[bi]; bq1[j] = wp3l[bi + 4 * PADN];
            }
#pragma unroll
            for (int j = 0; j < 4; j++) mma_bf16(C3[j], a3h[kk], bq0[j], bq1[j]);
        }

        // ---- epilogue: mu (tiles 0,1), sigma = softplus (tiles 2,3) ----
#pragma unroll
        for (int j = 0; j < 4; j++) {
            float v0 = C3[j][0], v1 = C3[j][1], v2 = C3[j][2], v3 = C3[j][3];
            size_t colbase;
            if (j < 2) {
                colbase = 8 * j + 2 * c;
            } else {
                v0 = softplus_f(v0); v1 = softplus_f(v1);
                v2 = softplus_f(v2); v3 = softplus_f(v3);
                colbase = (size_t)n * 16 + 8 * (j - 2) + 2 * c;
            }
            if (valid[0])
                *(float2*)(out + (size_t)rows[0] * 16 + colbase) = make_float2(v0, v1);
            if (valid[1])
                *(float2*)(out + (size_t)rows[1] * 16 + colbase) = make_float2(v2, v3);
        }
    }
}

// ---------------- launch ------------------------------------------------------
extern "C" void kernel_launch(void* const* d_in, const int* in_sizes, int n_in,
                              void* d_out, int out_size) {
    const float* x  = (const float*)d_in[0];
    const int*   y  = (const int*)d_in[1];
    const float* W1 = (const float*)d_in[2];
    const float* b1 = (const float*)d_in[3];
    const float* W2 = (const float*)d_in[4];
    const float* b2 = (const float*)d_in[5];
    const float* W3 = (const float*)d_in[6];
    const float* b3 = (const float*)d_in[7];
    float* out = (float*)d_out;
    int n = in_sizes[1];

    k_hist<<<512, 256>>>(y, n);
    k_scatter<<<(n + SC_ELEMS - 1) / SC_ELEMS, 256>>>(y, n);
    k_main<<<GRID, TPB>>>(x, W1, b1, W2, b2, W3, b3, out, n);
}

// round 9
// speedup vs baseline: 2.1438x; 1.2732x over previous
#include <cuda_runtime.h>
#include <cuda_fp16.h>
#include <stdint.h>
#include <math.h>

#define KEXP 8
#define NROWS_MAX 1000000
#define NSLICE 37
#define GRID (KEXP * NSLICE)
#define TPB 256
#define ROWS_PER_BLOCK 128   // 8 warps * 16 rows

// ---------------- device scratch ---------------------------------------------
__device__ int g_counts[KEXP];
__device__ int g_off[KEXP + 1];
__device__ int g_cursor[KEXP];
__device__ int g_ticket;
__device__ int g_perm[NROWS_MAX];

// ---------------- helpers -----------------------------------------------------
// pack two f32 -> f16x2 (first arg in low half)
__device__ __forceinline__ uint32_t pkh2(float lo, float hi) {
    uint32_t d;
    asm("cvt.rn.f16x2.f32 %0, %1, %2;" : "=r"(d) : "f"(hi), "f"(lo));
    return d;
}
// fp16 hi/lo split of a pair
__device__ __forceinline__ void split_pair(float v0, float v1,
                                           uint32_t& ph, uint32_t& pl) {
    ph = pkh2(v0, v1);
    __half2 h2 = *reinterpret_cast<__half2*>(&ph);
    float2 hf = __half22float2(h2);
    pl = pkh2(v0 - hf.x, v1 - hf.y);
}

__device__ __forceinline__ void mma_f16(float* C, const uint32_t* a,
                                        uint32_t b0, uint32_t b1) {
    asm volatile(
        "mma.sync.aligned.m16n8k16.row.col.f32.f16.f16.f32 "
        "{%0,%1,%2,%3}, {%4,%5,%6,%7}, {%8,%9}, {%0,%1,%2,%3};"
        : "+f"(C[0]), "+f"(C[1]), "+f"(C[2]), "+f"(C[3])
        : "r"(a[0]), "r"(a[1]), "r"(a[2]), "r"(a[3]), "r"(b0), "r"(b1));
}

__device__ __forceinline__ float softplus_f(float v) {
    return fmaxf(v, 0.f) + __logf(1.f + __expf(-fabsf(v)));
}

// ---------------- bucketing (proven kernels) ----------------------------------
__global__ void k_hist(const int* __restrict__ y, int n) {
    __shared__ int s[8][KEXP];
    int tid = threadIdx.x, wid = tid >> 5;
    if (tid < 8 * KEXP) ((int*)s)[tid] = 0;
    __syncthreads();
    int total = gridDim.x * blockDim.x;
    for (int i = blockIdx.x * blockDim.x + tid; i < n; i += total)
        atomicAdd(&s[wid][y[i]], 1);
    __syncthreads();
    if (tid < KEXP) {
        int acc = 0;
#pragma unroll
        for (int w = 0; w < 8; w++) acc += s[w][tid];
        atomicAdd(&g_counts[tid], acc);
    }
    __threadfence();
    if (tid == 0) {
        if (atomicAdd(&g_ticket, 1) == (int)gridDim.x - 1) {
            int o = 0;
#pragma unroll
            for (int k = 0; k < KEXP; k++) {
                g_off[k] = o;
                g_cursor[k] = o;
                o += g_counts[k];
                g_counts[k] = 0;   // reset for next graph replay
            }
            g_off[KEXP] = o;
            g_ticket = 0;
        }
    }
}

#define SC_ELEMS 2048
__global__ void k_scatter(const int* __restrict__ y, int n) {
    __shared__ int cache[SC_ELEMS];
    __shared__ int shist[KEXP];
    __shared__ int scur[KEXP];
    int base = blockIdx.x * SC_ELEMS;
    int cnt = n - base;
    if (cnt > SC_ELEMS) cnt = SC_ELEMS;
    if (cnt <= 0) return;
    int tid = threadIdx.x;
    if (tid < KEXP) shist[tid] = 0;
    __syncthreads();
    for (int i = tid; i < cnt; i += blockDim.x) {
        int k = y[base + i];
        cache[i] = k;
        atomicAdd(&shist[k], 1);
    }
    __syncthreads();
    if (tid < KEXP) scur[tid] = atomicAdd(&g_cursor[tid], shist[tid]);
    __syncthreads();
    for (int i = tid; i < cnt; i += blockDim.x) {
        int slot = atomicAdd(&scur[cache[i]], 1);
        g_perm[slot] = base + i;
    }
}

// ---------------- main mma.sync MLP kernel (2-pass fp16) ----------------------
#define PADN 72   // stride 72 words: bank = (8c+g) -> conflict-free

__global__ void __launch_bounds__(TPB, 2)
k_main(const float* __restrict__ x,
       const float* __restrict__ W1, const float* __restrict__ b1,
       const float* __restrict__ W2, const float* __restrict__ b2,
       const float* __restrict__ W3, const float* __restrict__ b3,
       float* __restrict__ out, int n)
{
    __shared__ uint32_t wp1[16 * PADN];   // W1 fp16, k-pair packed
    __shared__ uint32_t wp2[32 * PADN];   // W2 fp16
    __shared__ uint32_t wp3[32 * PADN];   // W3 fp16
    __shared__ float biasS[192];          // b1[0:64] b2[64:128] b3[128:160]

    int tid = threadIdx.x;
    int e = blockIdx.x & 7;
    int slice = blockIdx.x >> 3;

    const float* W1k = W1 + e * 2048;   // [32][64]
    const float* W2k = W2 + e * 4096;   // [64][64]
    const float* W3k = W3 + e * 2048;   // [64][32]

    // ---- stage weights as fp16, k-pair packed for B fragments ----
    for (int i = tid; i < 2048; i += TPB) {           // W1: K=32, N=64
        int k = i >> 6, nn = i & 63;
        int idx = ((k >> 1) * PADN + nn) * 2 + (k & 1);
        ((unsigned short*)wp1)[idx] = __half_as_ushort(__float2half_rn(W1k[i]));
    }
    for (int i = tid; i < 4096; i += TPB) {           // W2: K=64, N=64
        int k = i >> 6, nn = i & 63;
        int idx = ((k >> 1) * PADN + nn) * 2 + (k & 1);
        ((unsigned short*)wp2)[idx] = __half_as_ushort(__float2half_rn(W2k[i]));
    }
    for (int i = tid; i < 2048; i += TPB) {           // W3: K=64, N=32
        int k = i >> 5, nn = i & 31;
        int idx = ((k >> 1) * PADN + nn) * 2 + (k & 1);
        ((unsigned short*)wp3)[idx] = __half_as_ushort(__float2half_rn(W3k[i]));
    }
    if (tid < 64) biasS[tid] = b1[e * 64 + tid];
    else if (tid < 128) biasS[tid] = b2[e * 64 + (tid - 64)];
    else if (tid < 160) biasS[128 + tid - 128] = b3[e * 32 + (tid - 128)];
    __syncthreads();

    int w = tid >> 5;
    int lane = tid & 31;
    int g = lane >> 2;          // groupID (fragment row)
    int c = lane & 3;           // threadID in group (fragment col pair)

    int off0 = g_off[e];
    int cnt = g_off[e + 1] - off0;
    int ntile = (cnt + ROWS_PER_BLOCK - 1) >> 7;

    for (int t = slice; t < ntile; t += NSLICE) {
        int wbase = t * ROWS_PER_BLOCK + w * 16;
        if (wbase >= cnt) continue;

        int rows[2];
        bool valid[2];
#pragma unroll
        for (int hh = 0; hh < 2; hh++) {
            int gi = wbase + hh * 8 + g;
            valid[hh] = gi < cnt;
            rows[hh] = g_perm[off0 + (gi < cnt ? gi : cnt - 1)];
        }

        // ---- layer 1 A fragments from x (fp16 hi/lo split) ----
        uint32_t a1h[2][4], a1l[2][4];
#pragma unroll
        for (int hh = 0; hh < 2; hh++) {
            const float* xr = x + (size_t)rows[hh] * 32;
#pragma unroll
            for (int kk = 0; kk < 2; kk++) {
                float2 p0 = *(const float2*)(xr + 2 * c + 16 * kk);
                float2 p1 = *(const float2*)(xr + 2 * c + 8 + 16 * kk);
                split_pair(p0.x, p0.y, a1h[kk][hh],     a1l[kk][hh]);
                split_pair(p1.x, p1.y, a1h[kk][2 + hh], a1l[kk][2 + hh]);
            }
        }

        // ---- layer 1: [16x32] @ [32x64], 2 passes (ah + al) x wh ----
        float C1[8][4];
#pragma unroll
        for (int j = 0; j < 8; j++) {
            float2 bb = *(const float2*)(biasS + 8 * j + 2 * c);
            C1[j][0] = bb.x; C1[j][1] = bb.y; C1[j][2] = bb.x; C1[j][3] = bb.y;
        }
#pragma unroll
        for (int kk = 0; kk < 2; kk++) {
#pragma unroll
            for (int j = 0; j < 8; j++) {
                int bi = (8 * kk + c) * PADN + 8 * j + g;
                uint32_t b0 = wp1[bi], b1_ = wp1[bi + 4 * PADN];
                mma_f16(C1[j], a1h[kk], b0, b1_);
                mma_f16(C1[j], a1l[kk], b0, b1_);
            }
        }

        // ---- relu + convert -> layer 2 A ----
        uint32_t a2h[4][4], a2l[4][4];
#pragma unroll
        for (int j = 0; j < 8; j++) {
            float v0 = fmaxf(C1[j][0], 0.f);
            float v1 = fmaxf(C1[j][1], 0.f);
            float v2 = fmaxf(C1[j][2], 0.f);
            float v3 = fmaxf(C1[j][3], 0.f);
            int kk = j >> 1, half = j & 1;
            split_pair(v0, v1, a2h[kk][2 * half],     a2l[kk][2 * half]);
            split_pair(v2, v3, a2h[kk][2 * half + 1], a2l[kk][2 * half + 1]);
        }

        // ---- layer 2: [16x64] @ [64x64] ----
        float C2[8][4];
#pragma unroll
        for (int j = 0; j < 8; j++) {
            float2 bb = *(const float2*)(biasS + 64 + 8 * j + 2 * c);
            C2[j][0] = bb.x; C2[j][1] = bb.y; C2[j][2] = bb.x; C2[j][3] = bb.y;
        }
#pragma unroll
        for (int kk = 0; kk < 4; kk++) {
#pragma unroll
            for (int j = 0; j < 8; j++) {
                int bi = (8 * kk + c) * PADN + 8 * j + g;
                uint32_t b0 = wp2[bi], b1_ = wp2[bi + 4 * PADN];
                mma_f16(C2[j], a2h[kk], b0, b1_);
                mma_f16(C2[j], a2l[kk], b0, b1_);
            }
        }

        // ---- relu + convert -> layer 3 A ----
        uint32_t a3h[4][4], a3l[4][4];
#pragma unroll
        for (int j = 0; j < 8; j++) {
            float v0 = fmaxf(C2[j][0], 0.f);
            float v1 = fmaxf(C2[j][1], 0.f);
            float v2 = fmaxf(C2[j][2], 0.f);
            float v3 = fmaxf(C2[j][3], 0.f);
            int kk = j >> 1, half = j & 1;
            split_pair(v0, v1, a3h[kk][2 * half],     a3l[kk][2 * half]);
            split_pair(v2, v3, a3h[kk][2 * half + 1], a3l[kk][2 * half + 1]);
        }

        // ---- layer 3: [16x64] @ [64x32] ----
        float C3[4][4];
#pragma unroll
        for (int j = 0; j < 4; j++) {
            float2 bb = *(const float2*)(biasS + 128 + 8 * j + 2 * c);
            C3[j][0] = bb.x; C3[j][1] = bb.y; C3[j][2] = bb.x; C3[j][3] = bb.y;
        }
#pragma unroll
        for (int kk = 0; kk < 4; kk++) {
#pragma unroll
            for (int j = 0; j < 4; j++) {
                int bi = (8 * kk + c) * PADN + 8 * j + g;
                uint32_t b0 = wp3[bi], b1_ = wp3[bi + 4 * PADN];
                mma_f16(C3[j], a3h[kk], b0, b1_);
                mma_f16(C3[j], a3l[kk], b0, b1_);
            }
        }

        // ---- epilogue: mu (tiles 0,1), sigma = softplus (tiles 2,3) ----
#pragma unroll
        for (int j = 0; j < 4; j++) {
            float v0 = C3[j][0], v1 = C3[j][1], v2 = C3[j][2], v3 = C3[j][3];
            size_t colbase;
            if (j < 2) {
                colbase = 8 * j + 2 * c;
            } else {
                v0 = softplus_f(v0); v1 = softplus_f(v1);
                v2 = softplus_f(v2); v3 = softplus_f(v3);
                colbase = (size_t)n * 16 + 8 * (j - 2) + 2 * c;
            }
            if (valid[0])
                *(float2*)(out + (size_t)rows[0] * 16 + colbase) = make_float2(v0, v1);
            if (valid[1])
                *(float2*)(out + (size_t)rows[1] * 16 + colbase) = make_float2(v2, v3);
        }
    }
}

// ---------------- launch ------------------------------------------------------
extern "C" void kernel_launch(void* const* d_in, const int* in_sizes, int n_in,
                              void* d_out, int out_size) {
    const float* x  = (const float*)d_in[0];
    const int*   y  = (const int*)d_in[1];
    const float* W1 = (const float*)d_in[2];
    const float* b1 = (const float*)d_in[3];
    const float* W2 = (const float*)d_in[4];
    const float* b2 = (const float*)d_in[5];
    const float* W3 = (const float*)d_in[6];
    const float* b3 = (const float*)d_in[7];
    float* out = (float*)d_out;
    int n = in_sizes[1];

    k_hist<<<512, 256>>>(y, n);
    k_scatter<<<(n + SC_ELEMS - 1) / SC_ELEMS, 256>>>(y, n);
    k_main<<<GRID, TPB>>>(x, W1, b1, W2, b2, W3, b3, out, n);
}

// round 10
// speedup vs baseline: 2.7195x; 1.2685x over previous
#include <cuda_runtime.h>
#include <cuda_fp16.h>
#include <stdint.h>
#include <math.h>

#define KEXP 8
#define NROWS_MAX 1000000
#define NSLICE 37
#define GRID (KEXP * NSLICE)
#define TPB 256
#define ROWS_PER_BLOCK 128   // 8 warps * 16 rows

// ---------------- device scratch ---------------------------------------------
__device__ int g_counts[KEXP];
__device__ int g_off[KEXP + 1];
__device__ int g_cursor[KEXP];
__device__ int g_ticket;
__device__ int g_perm[NROWS_MAX];

// ---------------- helpers -----------------------------------------------------
// pack two f32 -> f16x2 (first arg in low half)
__device__ __forceinline__ uint32_t pkh2(float lo, float hi) {
    uint32_t d;
    asm("cvt.rn.f16x2.f32 %0, %1, %2;" : "=r"(d) : "f"(hi), "f"(lo));
    return d;
}

__device__ __forceinline__ void mma_f16(float* C, const uint32_t* a,
                                        uint32_t b0, uint32_t b1) {
    asm volatile(
        "mma.sync.aligned.m16n8k16.row.col.f32.f16.f16.f32 "
        "{%0,%1,%2,%3}, {%4,%5,%6,%7}, {%8,%9}, {%0,%1,%2,%3};"
        : "+f"(C[0]), "+f"(C[1]), "+f"(C[2]), "+f"(C[3])
        : "r"(a[0]), "r"(a[1]), "r"(a[2]), "r"(a[3]), "r"(b0), "r"(b1));
}

__device__ __forceinline__ float softplus_f(float v) {
    return fmaxf(v, 0.f) + __logf(1.f + __expf(-fabsf(v)));
}

// ---------------- bucketing (proven kernels) ----------------------------------
__global__ void k_hist(const int* __restrict__ y, int n) {
    __shared__ int s[8][KEXP];
    int tid = threadIdx.x, wid = tid >> 5;
    if (tid < 8 * KEXP) ((int*)s)[tid] = 0;
    __syncthreads();
    int total = gridDim.x * blockDim.x;
    for (int i = blockIdx.x * blockDim.x + tid; i < n; i += total)
        atomicAdd(&s[wid][y[i]], 1);
    __syncthreads();
    if (tid < KEXP) {
        int acc = 0;
#pragma unroll
        for (int w = 0; w < 8; w++) acc += s[w][tid];
        atomicAdd(&g_counts[tid], acc);
    }
    __threadfence();
    if (tid == 0) {
        if (atomicAdd(&g_ticket, 1) == (int)gridDim.x - 1) {
            int o = 0;
#pragma unroll
            for (int k = 0; k < KEXP; k++) {
                g_off[k] = o;
                g_cursor[k] = o;
                o += g_counts[k];
                g_counts[k] = 0;   // reset for next graph replay
            }
            g_off[KEXP] = o;
            g_ticket = 0;
        }
    }
}

#define SC_ELEMS 2048
__global__ void k_scatter(const int* __restrict__ y, int n) {
    __shared__ int cache[SC_ELEMS];
    __shared__ int shist[KEXP];
    __shared__ int scur[KEXP];
    int base = blockIdx.x * SC_ELEMS;
    int cnt = n - base;
    if (cnt > SC_ELEMS) cnt = SC_ELEMS;
    if (cnt <= 0) return;
    int tid = threadIdx.x;
    if (tid < KEXP) shist[tid] = 0;
    __syncthreads();
    for (int i = tid; i < cnt; i += blockDim.x) {
        int k = y[base + i];
        cache[i] = k;
        atomicAdd(&shist[k], 1);
    }
    __syncthreads();
    if (tid < KEXP) scur[tid] = atomicAdd(&g_cursor[tid], shist[tid]);
    __syncthreads();
    for (int i = tid; i < cnt; i += blockDim.x) {
        int slot = atomicAdd(&scur[cache[i]], 1);
        g_perm[slot] = base + i;
    }
}

// ---------------- main mma.sync MLP kernel (single-pass fp16) -----------------
#define PADN 72   // stride 72 words: bank = (8c+g) -> conflict-free

__global__ void __launch_bounds__(TPB, 2)
k_main(const float* __restrict__ x,
       const float* __restrict__ W1, const float* __restrict__ b1,
       const float* __restrict__ W2, const float* __restrict__ b2,
       const float* __restrict__ W3, const float* __restrict__ b3,
       float* __restrict__ out, int n)
{
    __shared__ uint32_t wp1[16 * PADN];   // W1 fp16, k-pair packed
    __shared__ uint32_t wp2[32 * PADN];   // W2 fp16
    __shared__ uint32_t wp3[32 * PADN];   // W3 fp16
    __shared__ float biasS[192];          // b1[0:64] b2[64:128] b3[128:160]

    int tid = threadIdx.x;
    int e = blockIdx.x & 7;
    int slice = blockIdx.x >> 3;

    const float* W1k = W1 + e * 2048;   // [32][64]
    const float* W2k = W2 + e * 4096;   // [64][64]
    const float* W3k = W3 + e * 2048;   // [64][32]

    // ---- stage weights as fp16, k-pair packed for B fragments ----
    for (int i = tid; i < 2048; i += TPB) {           // W1: K=32, N=64
        int k = i >> 6, nn = i & 63;
        int idx = ((k >> 1) * PADN + nn) * 2 + (k & 1);
        ((unsigned short*)wp1)[idx] = __half_as_ushort(__float2half_rn(W1k[i]));
    }
    for (int i = tid; i < 4096; i += TPB) {           // W2: K=64, N=64
        int k = i >> 6, nn = i & 63;
        int idx = ((k >> 1) * PADN + nn) * 2 + (k & 1);
        ((unsigned short*)wp2)[idx] = __half_as_ushort(__float2half_rn(W2k[i]));
    }
    for (int i = tid; i < 2048; i += TPB) {           // W3: K=64, N=32
        int k = i >> 5, nn = i & 31;
        int idx = ((k >> 1) * PADN + nn) * 2 + (k & 1);
        ((unsigned short*)wp3)[idx] = __half_as_ushort(__float2half_rn(W3k[i]));
    }
    if (tid < 64) biasS[tid] = b1[e * 64 + tid];
    else if (tid < 128) biasS[tid] = b2[e * 64 + (tid - 64)];
    else if (tid < 160) biasS[128 + tid - 128] = b3[e * 32 + (tid - 128)];
    __syncthreads();

    int w = tid >> 5;
    int lane = tid & 31;
    int g = lane >> 2;          // groupID (fragment row)
    int c = lane & 3;           // threadID in group (fragment col pair)

    int off0 = g_off[e];
    int cnt = g_off[e + 1] - off0;
    int ntile = (cnt + ROWS_PER_BLOCK - 1) >> 7;

    for (int t = slice; t < ntile; t += NSLICE) {
        int wbase = t * ROWS_PER_BLOCK + w * 16;
        if (wbase >= cnt) continue;

        int rows[2];
        bool valid[2];
#pragma unroll
        for (int hh = 0; hh < 2; hh++) {
            int gi = wbase + hh * 8 + g;
            valid[hh] = gi < cnt;
            rows[hh] = g_perm[off0 + (gi < cnt ? gi : cnt - 1)];
        }

        // ---- layer 1 A fragments from x (plain fp16) ----
        uint32_t a1[2][4];
#pragma unroll
        for (int hh = 0; hh < 2; hh++) {
            const float* xr = x + (size_t)rows[hh] * 32;
#pragma unroll
            for (int kk = 0; kk < 2; kk++) {
                float2 p0 = *(const float2*)(xr + 2 * c + 16 * kk);
                float2 p1 = *(const float2*)(xr + 2 * c + 8 + 16 * kk);
                a1[kk][hh]     = pkh2(p0.x, p0.y);
                a1[kk][2 + hh] = pkh2(p1.x, p1.y);
            }
        }

        // ---- layer 1: [16x32] @ [32x64], single pass ----
        float C1[8][4];
#pragma unroll
        for (int j = 0; j < 8; j++) {
            float2 bb = *(const float2*)(biasS + 8 * j + 2 * c);
            C1[j][0] = bb.x; C1[j][1] = bb.y; C1[j][2] = bb.x; C1[j][3] = bb.y;
        }
#pragma unroll
        for (int kk = 0; kk < 2; kk++) {
#pragma unroll
            for (int j = 0; j < 8; j++) {
                int bi = (8 * kk + c) * PADN + 8 * j + g;
                mma_f16(C1[j], a1[kk], wp1[bi], wp1[bi + 4 * PADN]);
            }
        }

        // ---- relu + convert -> layer 2 A ----
        uint32_t a2[4][4];
#pragma unroll
        for (int j = 0; j < 8; j++) {
            float v0 = fmaxf(C1[j][0], 0.f);
            float v1 = fmaxf(C1[j][1], 0.f);
            float v2 = fmaxf(C1[j][2], 0.f);
            float v3 = fmaxf(C1[j][3], 0.f);
            int kk = j >> 1, half = j & 1;
            a2[kk][2 * half]     = pkh2(v0, v1);
            a2[kk][2 * half + 1] = pkh2(v2, v3);
        }

        // ---- layer 2: [16x64] @ [64x64], single pass ----
        float C2[8][4];
#pragma unroll
        for (int j = 0; j < 8; j++) {
            float2 bb = *(const float2*)(biasS + 64 + 8 * j + 2 * c);
            C2[j][0] = bb.x; C2[j][1] = bb.y; C2[j][2] = bb.x; C2[j][3] = bb.y;
        }
#pragma unroll
        for (int kk = 0; kk < 4; kk++) {
#pragma unroll
            for (int j = 0; j < 8; j++) {
                int bi = (8 * kk + c) * PADN + 8 * j + g;
                mma_f16(C2[j], a2[kk], wp2[bi], wp2[bi + 4 * PADN]);
            }
        }

        // ---- relu + convert -> layer 3 A ----
        uint32_t a3[4][4];
#pragma unroll
        for (int j = 0; j < 8; j++) {
            float v0 = fmaxf(C2[j][0], 0.f);
            float v1 = fmaxf(C2[j][1], 0.f);
            float v2 = fmaxf(C2[j][2], 0.f);
            float v3 = fmaxf(C2[j][3], 0.f);
            int kk = j >> 1, half = j & 1;
            a3[kk][2 * half]     = pkh2(v0, v1);
            a3[kk][2 * half + 1] = pkh2(v2, v3);
        }

        // ---- layer 3: [16x64] @ [64x32], single pass ----
        float C3[4][4];
#pragma unroll
        for (int j = 0; j < 4; j++) {
            float2 bb = *(const float2*)(biasS + 128 + 8 * j + 2 * c);
            C3[j][0] = bb.x; C3[j][1] = bb.y; C3[j][2] = bb.x; C3[j][3] = bb.y;
        }
#pragma unroll
        for (int kk = 0; kk < 4; kk++) {
#pragma unroll
            for (int j = 0; j < 4; j++) {
                int bi = (8 * kk + c) * PADN + 8 * j + g;
                mma_f16(C3[j], a3[kk], wp3[bi], wp3[bi + 4 * PADN]);
            }
        }

        // ---- epilogue: mu (tiles 0,1), sigma = softplus (tiles 2,3) ----
#pragma unroll
        for (int j = 0; j < 4; j++) {
            float v0 = C3[j][0], v1 = C3[j][1], v2 = C3[j][2], v3 = C3[j][3];
            size_t colbase;
            if (j < 2) {
                colbase = 8 * j + 2 * c;
            } else {
                v0 = softplus_f(v0); v1 = softplus_f(v1);
                v2 = softplus_f(v2); v3 = softplus_f(v3);
                colbase = (size_t)n * 16 + 8 * (j - 2) + 2 * c;
            }
            if (valid[0])
                *(float2*)(out + (size_t)rows[0] * 16 + colbase) = make_float2(v0, v1);
            if (valid[1])
                *(float2*)(out + (size_t)rows[1] * 16 + colbase) = make_float2(v2, v3);
        }
    }
}

// ---------------- launch ------------------------------------------------------
extern "C" void kernel_launch(void* const* d_in, const int* in_sizes, int n_in,
                              void* d_out, int out_size) {
    const float* x  = (const float*)d_in[0];
    const int*   y  = (const int*)d_in[1];
    const float* W1 = (const float*)d_in[2];
    const float* b1 = (const float*)d_in[3];
    const float* W2 = (const float*)d_in[4];
    const float* b2 = (const float*)d_in[5];
    const float* W3 = (const float*)d_in[6];
    const float* b3 = (const float*)d_in[7];
    float* out = (float*)d_out;
    int n = in_sizes[1];

    k_hist<<<512, 256>>>(y, n);
    k_scatter<<<(n + SC_ELEMS - 1) / SC_ELEMS, 256>>>(y, n);
    k_main<<<GRID, TPB>>>(x, W1, b1, W2, b2, W3, b3, out, n);
}

// round 12
// speedup vs baseline: 3.0858x; 1.1347x over previous
#include <cuda_runtime.h>
#include <cuda_fp16.h>
#include <stdint.h>
#include <math.h>

#define KEXP 8
#define NROWS_MAX 1000000
#define NSLICE 37
#define GRID (KEXP * NSLICE)
#define TPB 256
#define ROWS_PER_BLOCK 256   // 8 warps * 32 rows

// ---------------- device scratch ---------------------------------------------
__device__ int g_counts[KEXP];
__device__ int g_off[KEXP + 1];
__device__ int g_cursor[KEXP];
__device__ int g_ticket;
__device__ int g_perm[NROWS_MAX];

// ---------------- helpers -----------------------------------------------------
__device__ __forceinline__ uint32_t pkh2(float lo, float hi) {
    uint32_t d;
    asm("cvt.rn.f16x2.f32 %0, %1, %2;" : "=r"(d) : "f"(hi), "f"(lo));
    return d;
}
__device__ __forceinline__ uint32_t relu2(uint32_t p) {
    uint32_t r;
    asm("max.f16x2 %0, %1, %2;" : "=r"(r) : "r"(p), "r"(0u));
    return r;
}

__device__ __forceinline__ void mma_f16(float* C, const uint32_t* a,
                                        uint32_t b0, uint32_t b1) {
    asm volatile(
        "mma.sync.aligned.m16n8k16.row.col.f32.f16.f16.f32 "
        "{%0,%1,%2,%3}, {%4,%5,%6,%7}, {%8,%9}, {%0,%1,%2,%3};"
        : "+f"(C[0]), "+f"(C[1]), "+f"(C[2]), "+f"(C[3])
        : "r"(a[0]), "r"(a[1]), "r"(a[2]), "r"(a[3]), "r"(b0), "r"(b1));
}

__device__ __forceinline__ float softplus_f(float v) {
    return fmaxf(v, 0.f) + __logf(1.f + __expf(-fabsf(v)));
}

// ---------------- bucketing (R10-proven kernels) ------------------------------
__global__ void k_hist(const int* __restrict__ y, int n) {
    __shared__ int s[8][KEXP];
    int tid = threadIdx.x, wid = tid >> 5;
    if (tid < 8 * KEXP) ((int*)s)[tid] = 0;
    __syncthreads();
    int total = gridDim.x * blockDim.x;
    for (int i = blockIdx.x * blockDim.x + tid; i < n; i += total)
        atomicAdd(&s[wid][y[i]], 1);
    __syncthreads();
    if (tid < KEXP) {
        int acc = 0;
#pragma unroll
        for (int w = 0; w < 8; w++) acc += s[w][tid];
        atomicAdd(&g_counts[tid], acc);
    }
    __threadfence();
    if (tid == 0) {
        if (atomicAdd(&g_ticket, 1) == (int)gridDim.x - 1) {
            int o = 0;
#pragma unroll
            for (int k = 0; k < KEXP; k++) {
                g_off[k] = o;
                g_cursor[k] = o;
                o += g_counts[k];
                g_counts[k] = 0;   // reset for next graph replay
            }
            g_off[KEXP] = o;
            g_ticket = 0;
        }
    }
}

#define SC_ELEMS 2048
__global__ void k_scatter(const int* __restrict__ y, int n) {
    __shared__ int cache[SC_ELEMS];
    __shared__ int shist[KEXP];
    __shared__ int scur[KEXP];
    int base = blockIdx.x * SC_ELEMS;
    int cnt = n - base;
    if (cnt > SC_ELEMS) cnt = SC_ELEMS;
    if (cnt <= 0) return;
    int tid = threadIdx.x;
    if (tid < KEXP) shist[tid] = 0;
    __syncthreads();
    for (int i = tid; i < cnt; i += blockDim.x) {
        int k = y[base + i];
        cache[i] = k;
        atomicAdd(&shist[k], 1);
    }
    __syncthreads();
    if (tid < KEXP) scur[tid] = atomicAdd(&g_cursor[tid], shist[tid]);
    __syncthreads();
    for (int i = tid; i < cnt; i += blockDim.x) {
        int slot = atomicAdd(&scur[cache[i]], 1);
        g_perm[slot] = base + i;
    }
}

// ---------------- main mma.sync MLP kernel (single-pass fp16, M=32/warp) ------
#define PADN 72   // stride 72 words: bank = (8c+g) -> conflict-free

__global__ void __launch_bounds__(TPB, 2)
k_main(const float* __restrict__ x,
       const float* __restrict__ W1, const float* __restrict__ b1,
       const float* __restrict__ W2, const float* __restrict__ b2,
       const float* __restrict__ W3, const float* __restrict__ b3,
       float* __restrict__ out, int n)
{
    __shared__ uint32_t wp1[16 * PADN];   // W1 fp16, k-pair packed
    __shared__ uint32_t wp2[32 * PADN];   // W2 fp16
    __shared__ uint32_t wp3[32 * PADN];   // W3 fp16
    __shared__ float biasS[192];          // b1[0:64] b2[64:128] b3[128:160]

    int tid = threadIdx.x;
    int e = blockIdx.x & 7;
    int slice = blockIdx.x >> 3;

    const float* W1k = W1 + e * 2048;   // [32][64]
    const float* W2k = W2 + e * 4096;   // [64][64]
    const float* W3k = W3 + e * 2048;   // [64][32]

    // ---- stage weights as fp16, k-pair packed for B fragments ----
    for (int i = tid; i < 2048; i += TPB) {           // W1: K=32, N=64
        int k = i >> 6, nn = i & 63;
        int idx = ((k >> 1) * PADN + nn) * 2 + (k & 1);
        ((unsigned short*)wp1)[idx] = __half_as_ushort(__float2half_rn(W1k[i]));
    }
    for (int i = tid; i < 4096; i += TPB) {           // W2: K=64, N=64
        int k = i >> 6, nn = i & 63;
        int idx = ((k >> 1) * PADN + nn) * 2 + (k & 1);
        ((unsigned short*)wp2)[idx] = __half_as_ushort(__float2half_rn(W2k[i]));
    }
    for (int i = tid; i < 2048; i += TPB) {           // W3: K=64, N=32
        int k = i >> 5, nn = i & 31;
        int idx = ((k >> 1) * PADN + nn) * 2 + (k & 1);
        ((unsigned short*)wp3)[idx] = __half_as_ushort(__float2half_rn(W3k[i]));
    }
    if (tid < 64) biasS[tid] = b1[e * 64 + tid];
    else if (tid < 128) biasS[tid] = b2[e * 64 + (tid - 64)];
    else if (tid < 160) biasS[128 + tid - 128] = b3[e * 32 + (tid - 128)];
    __syncthreads();

    int w = tid >> 5;
    int lane = tid & 31;
    int g = lane >> 2;          // groupID (fragment row)
    int c = lane & 3;           // threadID in group (fragment col pair)

    int off0 = g_off[e];
    int cnt = g_off[e + 1] - off0;
    int ntile = (cnt + ROWS_PER_BLOCK - 1) >> 8;

    for (int t = slice; t < ntile; t += NSLICE) {
        int wbase = t * ROWS_PER_BLOCK + w * 32;
        if (wbase >= cnt) continue;

        int rows[4];
        bool valid[4];
#pragma unroll
        for (int mh = 0; mh < 4; mh++) {
            int gi = wbase + (mh >> 1) * 16 + (mh & 1) * 8 + g;
            valid[mh] = gi < cnt;
            rows[mh] = g_perm[off0 + (gi < cnt ? gi : cnt - 1)];
        }

        // ---- layer 1 A fragments from x (plain fp16) ----
        uint32_t a1[2][2][4];
#pragma unroll
        for (int mm = 0; mm < 2; mm++) {
#pragma unroll
            for (int hh = 0; hh < 2; hh++) {
                const float* xr = x + (size_t)rows[mm * 2 + hh] * 32;
#pragma unroll
                for (int kk = 0; kk < 2; kk++) {
                    float2 p0 = *(const float2*)(xr + 2 * c + 16 * kk);
                    float2 p1 = *(const float2*)(xr + 2 * c + 8 + 16 * kk);
                    a1[mm][kk][hh]     = pkh2(p0.x, p0.y);
                    a1[mm][kk][2 + hh] = pkh2(p1.x, p1.y);
                }
            }
        }

        // ---- layer 1: [32x32] @ [32x64], single pass ----
        float C1[2][8][4];
#pragma unroll
        for (int j = 0; j < 8; j++) {
            float2 bb = *(const float2*)(biasS + 8 * j + 2 * c);
#pragma unroll
            for (int mm = 0; mm < 2; mm++) {
                C1[mm][j][0] = bb.x; C1[mm][j][1] = bb.y;
                C1[mm][j][2] = bb.x; C1[mm][j][3] = bb.y;
            }
        }
#pragma unroll
        for (int kk = 0; kk < 2; kk++) {
#pragma unroll
            for (int j = 0; j < 8; j++) {
                int bi = (8 * kk + c) * PADN + 8 * j + g;
                uint32_t b0 = wp1[bi], b1_ = wp1[bi + 4 * PADN];
                mma_f16(C1[0][j], a1[0][kk], b0, b1_);
                mma_f16(C1[1][j], a1[1][kk], b0, b1_);
            }
        }

        // ---- pack + packed relu -> layer 2 A ----
        uint32_t a2[2][4][4];
#pragma unroll
        for (int j = 0; j < 8; j++) {
            int kk = j >> 1, half = j & 1;
#pragma unroll
            for (int mm = 0; mm < 2; mm++) {
                a2[mm][kk][2 * half]     = relu2(pkh2(C1[mm][j][0], C1[mm][j][1]));
                a2[mm][kk][2 * half + 1] = relu2(pkh2(C1[mm][j][2], C1[mm][j][3]));
            }
        }

        // ---- layer 2: [32x64] @ [64x64], single pass ----
        float C2[2][8][4];
#pragma unroll
        for (int j = 0; j < 8; j++) {
            float2 bb = *(const float2*)(biasS + 64 + 8 * j + 2 * c);
#pragma unroll
            for (int mm = 0; mm < 2; mm++) {
                C2[mm][j][0] = bb.x; C2[mm][j][1] = bb.y;
                C2[mm][j][2] = bb.x; C2[mm][j][3] = bb.y;
            }
        }
#pragma unroll
        for (int kk = 0; kk < 4; kk++) {
#pragma unroll
            for (int j = 0; j < 8; j++) {
                int bi = (8 * kk + c) * PADN + 8 * j + g;
                uint32_t b0 = wp2[bi], b1_ = wp2[bi + 4 * PADN];
                mma_f16(C2[0][j], a2[0][kk], b0, b1_);
                mma_f16(C2[1][j], a2[1][kk], b0, b1_);
            }
        }

        // ---- pack + packed relu -> layer 3 A ----
        uint32_t a3[2][4][4];
#pragma unroll
        for (int j = 0; j < 8; j++) {
            int kk = j >> 1, half = j & 1;
#pragma unroll
            for (int mm = 0; mm < 2; mm++) {
                a3[mm][kk][2 * half]     = relu2(pkh2(C2[mm][j][0], C2[mm][j][1]));
                a3[mm][kk][2 * half + 1] = relu2(pkh2(C2[mm][j][2], C2[mm][j][3]));
            }
        }

        // ---- layer 3: [32x64] @ [64x32], single pass ----
        float C3[2][4][4];
#pragma unroll
        for (int j = 0; j < 4; j++) {
            float2 bb = *(const float2*)(biasS + 128 + 8 * j + 2 * c);
#pragma unroll
            for (int mm = 0; mm < 2; mm++) {
                C3[mm][j][0] = bb.x; C3[mm][j][1] = bb.y;
                C3[mm][j][2] = bb.x; C3[mm][j][3] = bb.y;
            }
        }
#pragma unroll
        for (int kk = 0; kk < 4; kk++) {
#pragma unroll
            for (int j = 0; j < 4; j++) {
                int bi = (8 * kk + c) * PADN + 8 * j + g;
                uint32_t b0 = wp3[bi], b1_ = wp3[bi + 4 * PADN];
                mma_f16(C3[0][j], a3[0][kk], b0, b1_);
                mma_f16(C3[1][j], a3[1][kk], b0, b1_);
            }
        }

        // ---- epilogue: mu (tiles 0,1), sigma = softplus (tiles 2,3) ----
#pragma unroll
        for (int mm = 0; mm < 2; mm++) {
#pragma unroll
            for (int j = 0; j < 4; j++) {
                float v0 = C3[mm][j][0], v1 = C3[mm][j][1];
                float v2 = C3[mm][j][2], v3 = C3[mm][j][3];
                size_t colbase;
                if (j < 2) {
                    colbase = 8 * j + 2 * c;
                } else {
                    v0 = softplus_f(v0); v1 = softplus_f(v1);
                    v2 = softplus_f(v2); v3 = softplus_f(v3);
                    colbase = (size_t)n * 16 + 8 * (j - 2) + 2 * c;
                }
                if (valid[mm * 2 + 0])
                    *(float2*)(out + (size_t)rows[mm * 2 + 0] * 16 + colbase) =
                        make_float2(v0, v1);
                if (valid[mm * 2 + 1])
                    *(float2*)(out + (size_t)rows[mm * 2 + 1] * 16 + colbase) =
                        make_float2(v2, v3);
            }
        }
    }
}

// ---------------- launch ------------------------------------------------------
extern "C" void kernel_launch(void* const* d_in, const int* in_sizes, int n_in,
                              void* d_out, int out_size) {
    const float* x  = (const float*)d_in[0];
    const int*   y  = (const int*)d_in[1];
    const float* W1 = (const float*)d_in[2];
    const float* b1 = (const float*)d_in[3];
    const float* W2 = (const float*)d_in[4];
    const float* b2 = (const float*)d_in[5];
    const float* W3 = (const float*)d_in[6];
    const float* b3 = (const float*)d_in[7];
    float* out = (float*)d_out;
    int n = in_sizes[1];

    k_hist<<<512, 256>>>(y, n);
    k_scatter<<<(n + SC_ELEMS - 1) / SC_ELEMS, 256>>>(y, n);
    k_main<<<GRID, TPB>>>(x, W1, b1, W2, b2, W3, b3, out, n);
}

// round 13
// speedup vs baseline: 3.1022x; 1.0053x over previous
#include <cuda_runtime.h>
#include <cuda_fp16.h>
#include <stdint.h>
#include <math.h>

#define KEXP 8
#define NROWS_MAX 1000000
#define NSLICE 37
#define GRID (KEXP * NSLICE)
#define TPB 256
#define ROWS_PER_BLOCK 256   // 8 warps * 32 rows

// ---------------- device scratch ---------------------------------------------
__device__ int g_counts[KEXP];
__device__ int g_off[KEXP + 1];
__device__ int g_cursor[KEXP];
__device__ int g_ticket;
__device__ int g_perm[NROWS_MAX];

// ---------------- helpers -----------------------------------------------------
__device__ __forceinline__ uint32_t pkh2(float lo, float hi) {
    uint32_t d;
    asm("cvt.rn.f16x2.f32 %0, %1, %2;" : "=r"(d) : "f"(hi), "f"(lo));
    return d;
}
__device__ __forceinline__ uint32_t relu2(uint32_t p) {
    uint32_t r;
    asm("max.f16x2 %0, %1, %2;" : "=r"(r) : "r"(p), "r"(0u));
    return r;
}

__device__ __forceinline__ void mma_f16(float* C, const uint32_t* a,
                                        uint32_t b0, uint32_t b1) {
    asm volatile(
        "mma.sync.aligned.m16n8k16.row.col.f32.f16.f16.f32 "
        "{%0,%1,%2,%3}, {%4,%5,%6,%7}, {%8,%9}, {%0,%1,%2,%3};"
        : "+f"(C[0]), "+f"(C[1]), "+f"(C[2]), "+f"(C[3])
        : "r"(a[0]), "r"(a[1]), "r"(a[2]), "r"(a[3]), "r"(b0), "r"(b1));
}

__device__ __forceinline__ float softplus_f(float v) {
    return fmaxf(v, 0.f) + __logf(1.f + __expf(-fabsf(v)));
}

// ---------------- bucketing ---------------------------------------------------
__global__ void k_hist(const int* __restrict__ y, int n) {
    __shared__ int s[8][KEXP];
    int tid = threadIdx.x, w = tid >> 5;
    if (tid < 8 * KEXP) ((int*)s)[tid] = 0;
    __syncthreads();
    int n4 = n >> 2;
    int total = gridDim.x * blockDim.x;
    for (int i = blockIdx.x * blockDim.x + tid; i < n4; i += total) {
        int4 v = ((const int4*)y)[i];
        atomicAdd(&s[w][v.x], 1);
        atomicAdd(&s[w][v.y], 1);
        atomicAdd(&s[w][v.z], 1);
        atomicAdd(&s[w][v.w], 1);
    }
    if (blockIdx.x == 0 && tid < (n & 3))           // tail elements
        atomicAdd(&s[w][y[(n4 << 2) + tid]], 1);
    __syncthreads();
    if (tid < KEXP) {
        int acc = 0;
#pragma unroll
        for (int ww = 0; ww < 8; ww++) acc += s[ww][tid];
        atomicAdd(&g_counts[tid], acc);
    }
    __threadfence();
    if (tid == 0) {
        if (atomicAdd(&g_ticket, 1) == (int)gridDim.x - 1) {
            int o = 0;
#pragma unroll
            for (int k = 0; k < KEXP; k++) {
                g_off[k] = o;
                g_cursor[k] = o;
                o += g_counts[k];
                g_counts[k] = 0;   // reset for next graph replay
            }
            g_off[KEXP] = o;
            g_ticket = 0;
        }
    }
}

#define SC_ELEMS 2048
__global__ void k_scatter(const int* __restrict__ y, int n) {
    __shared__ int whist[8][KEXP];   // per-warp counts
    __shared__ int wcur[8][KEXP];    // per-warp cursors (bases, then bumped)
    int base = blockIdx.x * SC_ELEMS;
    int cnt = n - base;
    if (cnt > SC_ELEMS) cnt = SC_ELEMS;
    if (cnt <= 0) return;
    int tid = threadIdx.x, w = tid >> 5;
    if (tid < 64) ((int*)whist)[tid] = 0;
    __syncthreads();

    // each thread: 8 elements via 2 int4 loads, cached in registers
    int ky[8];
    bool kv[8];
#pragma unroll
    for (int q = 0; q < 2; q++) {
        int i4 = tid + q * 256;      // int4 index within chunk
        int i = 4 * i4;
        if (i + 3 < cnt) {
            int4 v = ((const int4*)(y + base))[i4];
            ky[4 * q + 0] = v.x; ky[4 * q + 1] = v.y;
            ky[4 * q + 2] = v.z; ky[4 * q + 3] = v.w;
            kv[4 * q + 0] = kv[4 * q + 1] = kv[4 * q + 2] = kv[4 * q + 3] = true;
        } else {
#pragma unroll
            for (int r = 0; r < 4; r++) {
                int ii = i + r;
                kv[4 * q + r] = ii < cnt;
                ky[4 * q + r] = kv[4 * q + r] ? y[base + ii] : 0;
            }
        }
    }
#pragma unroll
    for (int q = 0; q < 8; q++)
        if (kv[q]) atomicAdd(&whist[w][ky[q]], 1);
    __syncthreads();

    // 8 threads compute per-warp bases from one global cursor bump per expert
    if (tid < KEXP) {
        int k = tid, tot = 0;
#pragma unroll
        for (int ww = 0; ww < 8; ww++) tot += whist[ww][k];
        int gb = atomicAdd(&g_cursor[k], tot);
#pragma unroll
        for (int ww = 0; ww < 8; ww++) {
            wcur[ww][k] = gb;
            gb += whist[ww][k];
        }
    }
    __syncthreads();

    // phase 3: warp-private cursor atomics (no cross-warp contention)
#pragma unroll
    for (int q = 0; q < 8; q++) {
        if (kv[q]) {
            int slot = atomicAdd(&wcur[w][ky[q]], 1);
            g_perm[slot] = base + 4 * (tid + (q >> 2) * 256) + (q & 3);
        }
    }
}

// ---------------- main mma.sync MLP kernel (single-pass fp16, M=32/warp) ------
#define PADN 72   // stride 72 words: bank = (8c+g) -> conflict-free

__global__ void __launch_bounds__(TPB, 2)
k_main(const float* __restrict__ x,
       const float* __restrict__ W1, const float* __restrict__ b1,
       const float* __restrict__ W2, const float* __restrict__ b2,
       const float* __restrict__ W3, const float* __restrict__ b3,
       float* __restrict__ out, int n)
{
    __shared__ uint32_t wp1[16 * PADN];   // W1 fp16, k-pair packed
    __shared__ uint32_t wp2[32 * PADN];   // W2 fp16
    __shared__ uint32_t wp3[32 * PADN];   // W3 fp16
    __shared__ float biasS[192];          // b1[0:64] b2[64:128] b3[128:160]

    int tid = threadIdx.x;
    int e = blockIdx.x & 7;
    int slice = blockIdx.x >> 3;

    const float* W1k = W1 + e * 2048;   // [32][64]
    const float* W2k = W2 + e * 4096;   // [64][64]
    const float* W3k = W3 + e * 2048;   // [64][32]

    // ---- stage weights as fp16, k-pair packed for B fragments ----
    for (int i = tid; i < 2048; i += TPB) {           // W1: K=32, N=64
        int k = i >> 6, nn = i & 63;
        int idx = ((k >> 1) * PADN + nn) * 2 + (k & 1);
        ((unsigned short*)wp1)[idx] = __half_as_ushort(__float2half_rn(W1k[i]));
    }
    for (int i = tid; i < 4096; i += TPB) {           // W2: K=64, N=64
        int k = i >> 6, nn = i & 63;
        int idx = ((k >> 1) * PADN + nn) * 2 + (k & 1);
        ((unsigned short*)wp2)[idx] = __half_as_ushort(__float2half_rn(W2k[i]));
    }
    for (int i = tid; i < 2048; i += TPB) {           // W3: K=64, N=32
        int k = i >> 5, nn = i & 31;
        int idx = ((k >> 1) * PADN + nn) * 2 + (k & 1);
        ((unsigned short*)wp3)[idx] = __half_as_ushort(__float2half_rn(W3k[i]));
    }
    if (tid < 64) biasS[tid] = b1[e * 64 + tid];
    else if (tid < 128) biasS[tid] = b2[e * 64 + (tid - 64)];
    else if (tid < 160) biasS[128 + tid - 128] = b3[e * 32 + (tid - 128)];
    __syncthreads();

    int w = tid >> 5;
    int lane = tid & 31;
    int g = lane >> 2;          // groupID (fragment row)
    int c = lane & 3;           // threadID in group (fragment col pair)

    int off0 = g_off[e];
    int cnt = g_off[e + 1] - off0;
    int ntile = (cnt + ROWS_PER_BLOCK - 1) >> 8;

    for (int t = slice; t < ntile; t += NSLICE) {
        int wbase = t * ROWS_PER_BLOCK + w * 32;
        if (wbase >= cnt) continue;

        int rows[4];
        bool valid[4];
#pragma unroll
        for (int mh = 0; mh < 4; mh++) {
            int gi = wbase + (mh >> 1) * 16 + (mh & 1) * 8 + g;
            valid[mh] = gi < cnt;
            rows[mh] = g_perm[off0 + (gi < cnt ? gi : cnt - 1)];
        }

        // ---- layer 1 A fragments from x (plain fp16) ----
        uint32_t a1[2][2][4];
#pragma unroll
        for (int mm = 0; mm < 2; mm++) {
#pragma unroll
            for (int hh = 0; hh < 2; hh++) {
                const float* xr = x + (size_t)rows[mm * 2 + hh] * 32;
#pragma unroll
                for (int kk = 0; kk < 2; kk++) {
                    float2 p0 = *(const float2*)(xr + 2 * c + 16 * kk);
                    float2 p1 = *(const float2*)(xr + 2 * c + 8 + 16 * kk);
                    a1[mm][kk][hh]     = pkh2(p0.x, p0.y);
                    a1[mm][kk][2 + hh] = pkh2(p1.x, p1.y);
                }
            }
        }

        // ---- layer 1: [32x32] @ [32x64], single pass ----
        float C1[2][8][4];
#pragma unroll
        for (int j = 0; j < 8; j++) {
            float2 bb = *(const float2*)(biasS + 8 * j + 2 * c);
#pragma unroll
            for (int mm = 0; mm < 2; mm++) {
                C1[mm][j][0] = bb.x; C1[mm][j][1] = bb.y;
                C1[mm][j][2] = bb.x; C1[mm][j][3] = bb.y;
            }
        }
#pragma unroll
        for (int kk = 0; kk < 2; kk++) {
#pragma unroll
            for (int j = 0; j < 8; j++) {
                int bi = (8 * kk + c) * PADN + 8 * j + g;
                uint32_t b0 = wp1[bi], b1_ = wp1[bi + 4 * PADN];
                mma_f16(C1[0][j], a1[0][kk], b0, b1_);
                mma_f16(C1[1][j], a1[1][kk], b0, b1_);
            }
        }

        // ---- pack + packed relu -> layer 2 A ----
        uint32_t a2[2][4][4];
#pragma unroll
        for (int j = 0; j < 8; j++) {
            int kk = j >> 1, half = j & 1;
#pragma unroll
            for (int mm = 0; mm < 2; mm++) {
                a2[mm][kk][2 * half]     = relu2(pkh2(C1[mm][j][0], C1[mm][j][1]));
                a2[mm][kk][2 * half + 1] = relu2(pkh2(C1[mm][j][2], C1[mm][j][3]));
            }
        }

        // ---- layer 2: [32x64] @ [64x64], single pass ----
        float C2[2][8][4];
#pragma unroll
        for (int j = 0; j < 8; j++) {
            float2 bb = *(const float2*)(biasS + 64 + 8 * j + 2 * c);
#pragma unroll
            for (int mm = 0; mm < 2; mm++) {
                C2[mm][j][0] = bb.x; C2[mm][j][1] = bb.y;
                C2[mm][j][2] = bb.x; C2[mm][j][3] = bb.y;
            }
        }
#pragma unroll
        for (int kk = 0; kk < 4; kk++) {
#pragma unroll
            for (int j = 0; j < 8; j++) {
                int bi = (8 * kk + c) * PADN + 8 * j + g;
                uint32_t b0 = wp2[bi], b1_ = wp2[bi + 4 * PADN];
                mma_f16(C2[0][j], a2[0][kk], b0, b1_);
                mma_f16(C2[1][j], a2[1][kk], b0, b1_);
            }
        }

        // ---- pack + packed relu -> layer 3 A ----
        uint32_t a3[2][4][4];
#pragma unroll
        for (int j = 0; j < 8; j++) {
            int kk = j >> 1, half = j & 1;
#pragma unroll
            for (int mm = 0; mm < 2; mm++) {
                a3[mm][kk][2 * half]     = relu2(pkh2(C2[mm][j][0], C2[mm][j][1]));
                a3[mm][kk][2 * half + 1] = relu2(pkh2(C2[mm][j][2], C2[mm][j][3]));
            }
        }

        // ---- layer 3: [32x64] @ [64x32], single pass ----
        float C3[2][4][4];
#pragma unroll
        for (int j = 0; j < 4; j++) {
            float2 bb = *(const float2*)(biasS + 128 + 8 * j + 2 * c);
#pragma unroll
            for (int mm = 0; mm < 2; mm++) {
                C3[mm][j][0] = bb.x; C3[mm][j][1] = bb.y;
                C3[mm][j][2] = bb.x; C3[mm][j][3] = bb.y;
            }
        }
#pragma unroll
        for (int kk = 0; kk < 4; kk++) {
#pragma unroll
            for (int j = 0; j < 4; j++) {
                int bi = (8 * kk + c) * PADN + 8 * j + g;
                uint32_t b0 = wp3[bi], b1_ = wp3[bi + 4 * PADN];
                mma_f16(C3[0][j], a3[0][kk], b0, b1_);
                mma_f16(C3[1][j], a3[1][kk], b0, b1_);
            }
        }

        // ---- epilogue: mu (tiles 0,1), sigma = softplus (tiles 2,3) ----
#pragma unroll
        for (int mm = 0; mm < 2; mm++) {
#pragma unroll
            for (int j = 0; j < 4; j++) {
                float v0 = C3[mm][j][0], v1 = C3[mm][j][1];
                float v2 = C3[mm][j][2], v3 = C3[mm][j][3];
                size_t colbase;
                if (j < 2) {
                    colbase = 8 * j + 2 * c;
                } else {
                    v0 = softplus_f(v0); v1 = softplus_f(v1);
                    v2 = softplus_f(v2); v3 = softplus_f(v3);
                    colbase = (size_t)n * 16 + 8 * (j - 2) + 2 * c;
                }
                if (valid[mm * 2 + 0])
                    *(float2*)(out + (size_t)rows[mm * 2 + 0] * 16 + colbase) =
                        make_float2(v0, v1);
                if (valid[mm * 2 + 1])
                    *(float2*)(out + (size_t)rows[mm * 2 + 1] * 16 + colbase) =
                        make_float2(v2, v3);
            }
        }
    }
}

// ---------------- launch ------------------------------------------------------
extern "C" void kernel_launch(void* const* d_in, const int* in_sizes, int n_in,
                              void* d_out, int out_size) {
    const float* x  = (const float*)d_in[0];
    const int*   y  = (const int*)d_in[1];
    const float* W1 = (const float*)d_in[2];
    const float* b1 = (const float*)d_in[3];
    const float* W2 = (const float*)d_in[4];
    const float* b2 = (const float*)d_in[5];
    const float* W3 = (const float*)d_in[6];
    const float* b3 = (const float*)d_in[7];
    float* out = (float*)d_out;
    int n = in_sizes[1];

    k_hist<<<512, 256>>>(y, n);
    k_scatter<<<(n + SC_ELEMS - 1) / SC_ELEMS, 256>>>(y, n);
    k_main<<<GRID, TPB>>>(x, W1, b1, W2, b2, W3, b3, out, n);
}